// round 12
// baseline (speedup 1.0000x reference)
#include <cuda_runtime.h>
#include <cstdint>

// Problem constants (fixed by setup_inputs)
#define B 8
#define L 2048
#define H 8
#define D 64
#define BH (B*H)

// Scratch (device globals — no allocation allowed)
__device__ float g_M[BH * L];          // sparsity measure per (b,h,q)
__device__ int   g_top[BH * 64];       // top-u query indices per (b,h)
__device__ float g_vpart[4 * BH * D];  // partial V sums (4 L-ranges)

// ---------------------------------------------------------------------------
// Kernel A v4: M[b,h,q] = max_s(QK_s) - mean_s(QK_s) over sampled keys.
// One warp per (b,h,q); each octet handles TWO samples per iteration
// (8 samples in flight per warp -> deeper MLP than v3's 4).
// ---------------------------------------------------------------------------
__global__ void __launch_bounds__(256) kA_mscore(
    const float* __restrict__ Q, const float* __restrict__ K,
    const int* __restrict__ idx, int SK)
{
    const unsigned F = 0xffffffffu;
    int gw   = (blockIdx.x * blockDim.x + threadIdx.x) >> 5;  // [0, BH*L)
    int lane = threadIdx.x & 31;
    int oct  = lane >> 3;          // 0..3
    int ld   = lane & 7;           // d-slice owner within octet
    int q  = gw & (L - 1);
    int bh = gw >> 11;
    int b  = bh >> 3, h = bh & 7;

    const float4* qp = (const float4*)(Q + ((size_t)(b * L + q) * H + h) * D);
    float4 qa = qp[ld], qb = qp[ld + 8];

    const int* ip = idx + (size_t)q * SK;
    int kq0 = (lane      < SK) ? ip[lane]      : 0;
    int kq1 = (lane + 32 < SK) ? ip[lane + 32] : 0;

    float mxA = -3.402823466e38f, smA = 0.f;
    float mxB = -3.402823466e38f, smB = 0.f;
    int iters = (SK + 7) >> 3;

    #pragma unroll 5
    for (int it = 0; it < iters; ++it) {
        int sA = it * 8 + oct;
        int sB = it * 8 + 4 + oct;
        int a0 = __shfl_sync(F, kq0, sA & 31);
        int a1 = __shfl_sync(F, kq1, sA & 31);
        int b0i = __shfl_sync(F, kq0, sB & 31);
        int b1i = __shfl_sync(F, kq1, sB & 31);
        int krA = (sA < 32) ? a0 : a1;
        int krB = (sB < 32) ? b0i : b1i;
        bool vA = (sA < SK), vB = (sB < SK);
        if (!vA) krA = 0;
        if (!vB) krB = 0;

        const float4* kpA = (const float4*)(K + ((size_t)(b * L + krA) * H + h) * D);
        const float4* kpB = (const float4*)(K + ((size_t)(b * L + krB) * H + h) * D);
        float4 ka0 = kpA[ld], ka1 = kpA[ld + 8];
        float4 kb0 = kpB[ld], kb1 = kpB[ld + 8];

        float xA = qa.x*ka0.x + qa.y*ka0.y + qa.z*ka0.z + qa.w*ka0.w
                 + qb.x*ka1.x + qb.y*ka1.y + qb.z*ka1.z + qb.w*ka1.w;
        float xB = qa.x*kb0.x + qa.y*kb0.y + qa.z*kb0.z + qa.w*kb0.w
                 + qb.x*kb1.x + qb.y*kb1.y + qb.z*kb1.z + qb.w*kb1.w;

        xA += __shfl_xor_sync(F, xA, 4);
        xB += __shfl_xor_sync(F, xB, 4);
        xA += __shfl_xor_sync(F, xA, 2);
        xB += __shfl_xor_sync(F, xB, 2);
        xA += __shfl_xor_sync(F, xA, 1);
        xB += __shfl_xor_sync(F, xB, 1);

        if (vA) { mxA = fmaxf(mxA, xA); smA += xA; }
        if (vB) { mxB = fmaxf(mxB, xB); smB += xB; }
    }

    float mx = fmaxf(mxA, mxB);
    float sm = smA + smB;
    // combine the 4 octet accumulators (lanes within an octet identical)
    mx = fmaxf(mx, __shfl_xor_sync(F, mx, 8));
    mx = fmaxf(mx, __shfl_xor_sync(F, mx, 16));
    sm += __shfl_xor_sync(F, sm, 8);
    sm += __shfl_xor_sync(F, sm, 16);

    if (lane == 0)
        g_M[gw] = mx - sm / (float)SK;
}

// ---------------------------------------------------------------------------
// Kernel B: top-U per (b,h), register-resident 64-bit sortable keys.
// key = (ordered(value) << 32) | ~index  -> max picks higher value, lower idx.
// ---------------------------------------------------------------------------
__global__ void __launch_bounds__(256) kB_topk(int U)
{
    __shared__ unsigned long long warpbest[8];
    __shared__ unsigned long long sbest;
    int bh = blockIdx.x, t = threadIdx.x, lane = t & 31, w = t >> 5;

    unsigned long long key[8];
    #pragma unroll
    for (int i = 0; i < 8; ++i) {
        int q = t + i * 256;
        unsigned u = __float_as_uint(g_M[(size_t)bh * L + q]);
        u ^= (u >> 31) ? 0xffffffffu : 0x80000000u;
        key[i] = ((unsigned long long)u << 32) | (unsigned)(~q);
    }

    for (int it = 0; it < U; ++it) {
        unsigned long long best = 0;
        #pragma unroll
        for (int i = 0; i < 8; ++i) best = (key[i] > best) ? key[i] : best;
        #pragma unroll
        for (int o = 16; o; o >>= 1) {
            unsigned long long oth = __shfl_xor_sync(0xffffffffu, best, o);
            best = (oth > best) ? oth : best;
        }
        if (lane == 0) warpbest[w] = best;
        __syncthreads();
        if (t < 32) {
            unsigned long long bb = (t < 8) ? warpbest[t] : 0ull;
            #pragma unroll
            for (int o = 4; o; o >>= 1) {
                unsigned long long oth = __shfl_xor_sync(0xffffffffu, bb, o);
                bb = (oth > bb) ? oth : bb;
            }
            if (t == 0) {
                sbest = bb;
                g_top[bh * 64 + it] = (int)(~(unsigned)(bb & 0xffffffffu));
            }
        }
        __syncthreads();
        unsigned long long win = sbest;
        #pragma unroll
        for (int i = 0; i < 8; ++i) if (key[i] == win) key[i] = 0ull;
    }
}

// ---------------------------------------------------------------------------
// Kernel C v2: partial V sums over 4 L-ranges. 256 blocks (bh, range).
// ---------------------------------------------------------------------------
__global__ void __launch_bounds__(256) kC_vmean(const float* __restrict__ V)
{
    __shared__ float part[4][D];
    int bh = blockIdx.x & 63, r = blockIdx.x >> 6;
    int b = bh >> 3, h = bh & 7;
    int d = threadIdx.x & 63, g = threadIdx.x >> 6;
    float s = 0.f;
    int l0 = r * 512 + g;
    for (int l = l0; l < r * 512 + 512; l += 4)
        s += V[((size_t)(b * L + l) * H + h) * D + d];
    part[g][d] = s;
    __syncthreads();
    if (threadIdx.x < D)
        g_vpart[((size_t)r * BH + bh) * D + d]
            = part[0][d] + part[1][d] + part[2][d] + part[3][d];
}

// ---------------------------------------------------------------------------
// Kernel D v3: fill output with broadcast Vmean computed from 4 partials.
// ---------------------------------------------------------------------------
__global__ void __launch_bounds__(256) kD_fill(float4* __restrict__ out4)
{
    int i = blockIdx.x * blockDim.x + threadIdx.x;     // [0, B*L*128)
    int j   = i & 127;
    int row = i >> 7;
    int b = row >> 11;
    int h = j >> 4, d4 = j & 15;
    const float4* vp = (const float4*)g_vpart;
    int base = (b * H + h) * 16 + d4;
    float4 s0 = vp[0 * BH * 16 + base];
    float4 s1 = vp[1 * BH * 16 + base];
    float4 s2 = vp[2 * BH * 16 + base];
    float4 s3 = vp[3 * BH * 16 + base];
    float4 r;
    const float inv = 1.0f / (float)L;
    r.x = (s0.x + s1.x + s2.x + s3.x) * inv;
    r.y = (s0.y + s1.y + s2.y + s3.y) * inv;
    r.z = (s0.z + s1.z + s2.z + s3.z) * inv;
    r.w = (s0.w + s1.w + s2.w + s3.w) * inv;
    out4[i] = r;
}

// ---------------------------------------------------------------------------
// Kernel E v2: full attention for 8 selected queries per block.
// Pass 1 stages K in 128-row smem tiles (coalesced) and computes scores with
// a broadcast-friendly (q = t&7, k = t>>3) assignment -> no 32-line sectoring.
// p rows padded to PL=2052 so score stores are bank-conflict-free.
// ---------------------------------------------------------------------------
#define UQ 8
#define KT 128
#define KPAD 68
#define PL (L + 4)
#define SMEM_E ((UQ*PL + UQ*KPAD + KT*KPAD + 4*UQ*D + UQ) * 4)

__global__ void __launch_bounds__(256) kE_attn(
    const float* __restrict__ Q, const float* __restrict__ K,
    const float* __restrict__ V, float* __restrict__ out, int U, int UT)
{
    extern __shared__ float sh[];
    float* p    = sh;                    // [UQ][PL] unnormalized probs
    float* Qs   = p + UQ * PL;           // [UQ][KPAD]
    float* sKt  = Qs + UQ * KPAD;        // [KT][KPAD]
    float* red  = sKt + KT * KPAD;       // [4][UQ][D]
    float* sden = red + 4 * UQ * D;      // [UQ]
    __shared__ int qidx[UQ];

    int bh = blockIdx.x / UT, ut = blockIdx.x % UT;
    int b = bh >> 3, h = bh & 7;
    int t = threadIdx.x;
    int u0 = ut * UQ;
    int nq = U - u0; if (nq > UQ) nq = UQ;

    if (t < UQ) qidx[t] = (t < nq) ? g_top[bh * 64 + u0 + t] : 0;
    __syncthreads();

    // Load Q rows (padded rows, float4)
    if (t < UQ * 16) {
        int j = t >> 4, c4 = t & 15;
        float4 v = make_float4(0.f, 0.f, 0.f, 0.f);
        if (j < nq)
            v = *(const float4*)&Q[((size_t)(b * L + qidx[j]) * H + h) * D + c4 * 4];
        *(float4*)&Qs[j * KPAD + c4 * 4] = v;
    }

    // Pass 1: scores via smem-staged K tiles.
    const float scale = 0.125f;  // 1/sqrt(64)
    int qj   = t & 7;
    int kloc = t >> 3;           // 0..31
    for (int kt = 0; kt < L / KT; ++kt) {
        __syncthreads();         // covers Q load (first iter) and sKt reuse
        for (int i = t; i < KT * 16; i += 256) {
            int r = i >> 4, c4 = i & 15;
            float4 v = *(const float4*)&K[((size_t)(b * L + kt * KT + r) * H + h) * D + c4 * 4];
            *(float4*)&sKt[r * KPAD + c4 * 4] = v;
        }
        __syncthreads();

        float acc0 = 0.f, acc1 = 0.f, acc2 = 0.f, acc3 = 0.f;
        #pragma unroll
        for (int c = 0; c < 16; ++c) {
            float4 qf = *(const float4*)&Qs[qj * KPAD + c * 4];
            float4 k0 = *(const float4*)&sKt[(kloc +  0) * KPAD + c * 4];
            float4 k1 = *(const float4*)&sKt[(kloc + 32) * KPAD + c * 4];
            float4 k2 = *(const float4*)&sKt[(kloc + 64) * KPAD + c * 4];
            float4 k3 = *(const float4*)&sKt[(kloc + 96) * KPAD + c * 4];
            acc0 += qf.x*k0.x + qf.y*k0.y + qf.z*k0.z + qf.w*k0.w;
            acc1 += qf.x*k1.x + qf.y*k1.y + qf.z*k1.z + qf.w*k1.w;
            acc2 += qf.x*k2.x + qf.y*k2.y + qf.z*k2.z + qf.w*k2.w;
            acc3 += qf.x*k3.x + qf.y*k3.y + qf.z*k3.z + qf.w*k3.w;
        }
        int kbase = kt * KT + kloc;
        p[qj * PL + kbase +  0] = acc0 * scale;
        p[qj * PL + kbase + 32] = acc1 * scale;
        p[qj * PL + kbase + 64] = acc2 * scale;
        p[qj * PL + kbase + 96] = acc3 * scale;
    }
    __syncthreads();

    // Pass 2: softmax per query row (warp w handles row w).
    int w = t >> 5, lane = t & 31;
    if (w < nq) {
        float* pr = p + w * PL;
        float m = -3.402823466e38f;
        for (int k = lane; k < L; k += 32) m = fmaxf(m, pr[k]);
        #pragma unroll
        for (int o = 16; o; o >>= 1) m = fmaxf(m, __shfl_xor_sync(0xffffffffu, m, o));
        float s = 0.f;
        for (int k = lane; k < L; k += 32) {
            float e = __expf(pr[k] - m);
            pr[k] = e;
            s += e;
        }
        #pragma unroll
        for (int o = 16; o; o >>= 1) s += __shfl_xor_sync(0xffffffffu, s, o);
        if (lane == 0) sden[w] = s;
    }
    __syncthreads();

    // Pass 3: ctx[j][d] = sum_k p[j][k] * V[k][d]
    int d = t & 63, g = t >> 6;
    float acc[UQ];
    #pragma unroll
    for (int j = 0; j < UQ; ++j) acc[j] = 0.f;
    for (int kb = g * 4; kb < L; kb += 16) {
        size_t vb = ((size_t)(b * L + kb) * H + h) * D + d;
        float v0 = V[vb];
        float v1 = V[vb + (size_t)H * D];
        float v2 = V[vb + (size_t)2 * H * D];
        float v3 = V[vb + (size_t)3 * H * D];
        #pragma unroll
        for (int j = 0; j < UQ; ++j) {
            float4 pv = *(const float4*)(p + j * PL + kb);   // warp-uniform broadcast
            acc[j] += pv.x * v0 + pv.y * v1 + pv.z * v2 + pv.w * v3;
        }
    }
    #pragma unroll
    for (int j = 0; j < UQ; ++j) red[(g * UQ + j) * D + d] = acc[j];
    __syncthreads();

    for (int i = t; i < nq * D; i += 256) {
        int j = i >> 6, dd = i & 63;
        float s = red[(0 * UQ + j) * D + dd] + red[(1 * UQ + j) * D + dd]
                + red[(2 * UQ + j) * D + dd] + red[(3 * UQ + j) * D + dd];
        out[((size_t)(b * L + qidx[j]) * H + h) * D + dd] = s / sden[j];
    }
}

// ---------------------------------------------------------------------------
extern "C" void kernel_launch(void* const* d_in, const int* in_sizes, int n_in,
                              void* d_out, int out_size)
{
    const float* Q   = (const float*)d_in[0];
    const float* K   = (const float*)d_in[1];
    const float* V   = (const float*)d_in[2];
    const int*   idx = (const int*)d_in[3];
    float* out = (float*)d_out;

    int SK = in_sizes[3] / L;     // sample_k (= 40)
    int U  = SK;
    if (U > 64) U = 64;
    int UT = (U + UQ - 1) / UQ;

    // A: M scores (octet-parallel gather, 8 samples in flight per warp)
    kA_mscore<<<(BH * L) / 8, 256>>>(Q, K, idx, SK);
    // C: partial V sums (256 blocks)
    kC_vmean<<<4 * BH, 256>>>(V);
    // B: top-U query selection per (b,h)
    kB_topk<<<BH, 256>>>(U);
    // D: broadcast-fill output (computes mean from 4 partials)
    kD_fill<<<(B * L * 128) / 256, 256>>>((float4*)out);
    // E: full attention for selected queries, overwrite their rows
    cudaFuncSetAttribute(kE_attn, cudaFuncAttributeMaxDynamicSharedMemorySize, SMEM_E);
    kE_attn<<<BH * UT, 256, SMEM_E>>>(Q, K, V, out, U, UT);
}

// round 13
// speedup vs baseline: 1.0446x; 1.0446x over previous
#include <cuda_runtime.h>
#include <cstdint>

// Problem constants (fixed by setup_inputs)
#define B 8
#define L 2048
#define H 8
#define D 64
#define BH (B*H)

// Scratch (device globals — no allocation allowed)
__device__ float g_M[BH * L];        // sparsity measure per (b,h,q)
__device__ int   g_top[BH * 64];     // top-u query indices per (b,h)
__device__ float g_vmean[BH * D];    // mean of V over L per (b,h,d)

// ---------------------------------------------------------------------------
// Kernel A v3 (R7-measured): M[b,h,q] = max_s(QK_s) - mean_s(QK_s).
// One warp per (b,h,q); each octet handles one sample -> 4 in flight.
// ---------------------------------------------------------------------------
__global__ void __launch_bounds__(256) kA_mscore(
    const float* __restrict__ Q, const float* __restrict__ K,
    const int* __restrict__ idx, int SK)
{
    const unsigned F = 0xffffffffu;
    int gw   = (blockIdx.x * blockDim.x + threadIdx.x) >> 5;  // [0, BH*L)
    int lane = threadIdx.x & 31;
    int oct  = lane >> 3;
    int ld   = lane & 7;
    int q  = gw & (L - 1);
    int bh = gw >> 11;
    int b  = bh >> 3, h = bh & 7;

    const float4* qp = (const float4*)(Q + ((size_t)(b * L + q) * H + h) * D);
    float4 qa = qp[ld], qb = qp[ld + 8];

    const int* ip = idx + (size_t)q * SK;
    int kq0 = (lane      < SK) ? ip[lane]      : 0;
    int kq1 = (lane + 32 < SK) ? ip[lane + 32] : 0;

    float mx = -3.402823466e38f, sm = 0.f;
    int iters = (SK + 3) >> 2;

    #pragma unroll 5
    for (int it = 0; it < iters; ++it) {
        int s  = it * 4 + oct;
        int i0 = __shfl_sync(F, kq0, s & 31);
        int i1 = __shfl_sync(F, kq1, s & 31);
        int kr = (s < 32) ? i0 : i1;
        bool valid = (s < SK);
        if (!valid) kr = 0;

        const float4* kp = (const float4*)(K + ((size_t)(b * L + kr) * H + h) * D);
        float4 ka = kp[ld], kb = kp[ld + 8];
        float x = qa.x*ka.x + qa.y*ka.y + qa.z*ka.z + qa.w*ka.w
                + qb.x*kb.x + qb.y*kb.y + qb.z*kb.z + qb.w*kb.w;
        x += __shfl_xor_sync(F, x, 4);
        x += __shfl_xor_sync(F, x, 2);
        x += __shfl_xor_sync(F, x, 1);
        if (valid) { mx = fmaxf(mx, x); sm += x; }
    }

    mx = fmaxf(mx, __shfl_xor_sync(F, mx, 8));
    mx = fmaxf(mx, __shfl_xor_sync(F, mx, 16));
    sm += __shfl_xor_sync(F, sm, 8);
    sm += __shfl_xor_sync(F, sm, 16);

    if (lane == 0)
        g_M[gw] = mx - sm / (float)SK;
}

// ---------------------------------------------------------------------------
// Kernel B: top-U per (b,h), register-resident 64-bit sortable keys.
// ---------------------------------------------------------------------------
__global__ void __launch_bounds__(256) kB_topk(int U)
{
    __shared__ unsigned long long warpbest[8];
    __shared__ unsigned long long sbest;
    int bh = blockIdx.x, t = threadIdx.x, lane = t & 31, w = t >> 5;

    unsigned long long key[8];
    #pragma unroll
    for (int i = 0; i < 8; ++i) {
        int q = t + i * 256;
        unsigned u = __float_as_uint(g_M[(size_t)bh * L + q]);
        u ^= (u >> 31) ? 0xffffffffu : 0x80000000u;
        key[i] = ((unsigned long long)u << 32) | (unsigned)(~q);
    }

    for (int it = 0; it < U; ++it) {
        unsigned long long best = 0;
        #pragma unroll
        for (int i = 0; i < 8; ++i) best = (key[i] > best) ? key[i] : best;
        #pragma unroll
        for (int o = 16; o; o >>= 1) {
            unsigned long long oth = __shfl_xor_sync(0xffffffffu, best, o);
            best = (oth > best) ? oth : best;
        }
        if (lane == 0) warpbest[w] = best;
        __syncthreads();
        if (t < 32) {
            unsigned long long bb = (t < 8) ? warpbest[t] : 0ull;
            #pragma unroll
            for (int o = 4; o; o >>= 1) {
                unsigned long long oth = __shfl_xor_sync(0xffffffffu, bb, o);
                bb = (oth > bb) ? oth : bb;
            }
            if (t == 0) {
                sbest = bb;
                g_top[bh * 64 + it] = (int)(~(unsigned)(bb & 0xffffffffu));
            }
        }
        __syncthreads();
        unsigned long long win = sbest;
        #pragma unroll
        for (int i = 0; i < 8; ++i) if (key[i] == win) key[i] = 0ull;
    }
}

// ---------------------------------------------------------------------------
// Kernel C: Vmean[b,h,d] = mean over l of V[b,l,h,d]. One block per (b,h).
// ---------------------------------------------------------------------------
__global__ void __launch_bounds__(256) kC_vmean(const float* __restrict__ V)
{
    __shared__ float part[4][D];
    int bh = blockIdx.x, b = bh >> 3, h = bh & 7;
    int d = threadIdx.x & 63, g = threadIdx.x >> 6;
    float s = 0.f;
    for (int l = g; l < L; l += 4)
        s += V[((size_t)(b * L + l) * H + h) * D + d];
    part[g][d] = s;
    __syncthreads();
    if (threadIdx.x < D) {
        float tot = part[0][d] + part[1][d] + part[2][d] + part[3][d];
        g_vmean[bh * D + d] = tot * (1.0f / (float)L);
    }
}

// ---------------------------------------------------------------------------
// Kernel D: fill output with broadcast Vmean (1 float4 per thread).
// ---------------------------------------------------------------------------
__global__ void __launch_bounds__(256) kD_fill(float4* __restrict__ out4)
{
    int i = blockIdx.x * blockDim.x + threadIdx.x;     // [0, B*L*128)
    int j   = i & 127;
    int row = i >> 7;
    int b = row >> 11;
    int h = j >> 4, d4 = j & 15;
    const float4* vm4 = (const float4*)g_vmean;
    out4[i] = vm4[(b * H + h) * 16 + d4];
}

// ---------------------------------------------------------------------------
// Kernel E v3: full attention for 8 selected queries per block.
// Pass 1: octet-cooperative K-row loads (4 lines/LDG, not 32) with Q in
// registers and a 7-shfl butterfly that lands dot(Q[j],K[k]) on lane j.
// p rows padded to PL=2052 -> conflict-free stores. Pass 2/3 as before.
// ---------------------------------------------------------------------------
#define UQ 8
#define PL (L + 4)
#define SMEM_E ((UQ*PL + UQ*D + 4*UQ*D + UQ) * 4)

__global__ void __launch_bounds__(256) kE_attn(
    const float* __restrict__ Q, const float* __restrict__ K,
    const float* __restrict__ V, float* __restrict__ out, int U, int UT)
{
    extern __shared__ float sh[];
    float* p    = sh;                    // [UQ][PL] unnormalized probs
    float* Qs   = p + UQ * PL;           // [UQ][D]
    float* red  = Qs + UQ * D;           // [4][UQ][D]
    float* sden = red + 4 * UQ * D;      // [UQ]
    __shared__ int qidx[UQ];

    int bh = blockIdx.x / UT, ut = blockIdx.x % UT;
    int b = bh >> 3, h = bh & 7;
    int t = threadIdx.x;
    int u0 = ut * UQ;
    int nq = U - u0; if (nq > UQ) nq = UQ;

    if (t < UQ) qidx[t] = (t < nq) ? g_top[bh * 64 + u0 + t] : 0;
    __syncthreads();

    for (int i = t; i < UQ * D; i += 256) {
        int j = i >> 6;
        Qs[i] = (j < nq) ? Q[((size_t)(b * L + qidx[j]) * H + h) * D + (i & 63)] : 0.f;
    }
    __syncthreads();

    // Pass 1: octet-cooperative scores.
    const unsigned F = 0xffffffffu;
    int w = t >> 5, lane = t & 31, oct = lane >> 3, ld = lane & 7;
    float4 qA[UQ], qB[UQ];
    #pragma unroll
    for (int j = 0; j < UQ; ++j) {
        qA[j] = *(const float4*)&Qs[j * D + ld * 4];
        qB[j] = *(const float4*)&Qs[j * D + 32 + ld * 4];
    }
    const float scale = 0.125f;  // 1/sqrt(64)
    bool hi4 = (ld & 4) != 0;
    bool hi2 = (ld & 2) != 0;
    bool hi1 = (ld & 1) != 0;

    #pragma unroll 2
    for (int it = 0; it < 64; ++it) {
        int k = w * 256 + it * 4 + oct;
        const float4* kp = (const float4*)(K + ((size_t)(b * L + k) * H + h) * D);
        float4 ka = kp[ld], kb = kp[ld + 8];

        float x[UQ];
        #pragma unroll
        for (int j = 0; j < UQ; ++j)
            x[j] = qA[j].x*ka.x + qA[j].y*ka.y + qA[j].z*ka.z + qA[j].w*ka.w
                 + qB[j].x*kb.x + qB[j].y*kb.y + qB[j].z*kb.z + qB[j].w*kb.w;

        // butterfly tree: lane ld ends with sum over octet of x[ld]
        float y[4];
        #pragma unroll
        for (int j = 0; j < 4; ++j) {
            float send = hi4 ? x[j] : x[j + 4];
            float keep = hi4 ? x[j + 4] : x[j];
            y[j] = keep + __shfl_xor_sync(F, send, 4);
        }
        float z[2];
        #pragma unroll
        for (int j = 0; j < 2; ++j) {
            float send = hi2 ? y[j] : y[j + 2];
            float keep = hi2 ? y[j + 2] : y[j];
            z[j] = keep + __shfl_xor_sync(F, send, 2);
        }
        float send = hi1 ? z[0] : z[1];
        float keep = hi1 ? z[1] : z[0];
        float tot = keep + __shfl_xor_sync(F, send, 1);

        p[ld * PL + w * 256 + it * 4 + oct] = tot * scale;
    }
    __syncthreads();

    // Pass 2: softmax per query row (warp w handles row w).
    if (w < nq) {
        float* pr = p + w * PL;
        float m = -3.402823466e38f;
        for (int k = lane; k < L; k += 32) m = fmaxf(m, pr[k]);
        #pragma unroll
        for (int o = 16; o; o >>= 1) m = fmaxf(m, __shfl_xor_sync(0xffffffffu, m, o));
        float s = 0.f;
        for (int k = lane; k < L; k += 32) {
            float e = __expf(pr[k] - m);
            pr[k] = e;
            s += e;
        }
        #pragma unroll
        for (int o = 16; o; o >>= 1) s += __shfl_xor_sync(0xffffffffu, s, o);
        if (lane == 0) sden[w] = s;
    }
    __syncthreads();

    // Pass 3: ctx[j][d] = sum_k p[j][k] * V[k][d]
    int d = t & 63, g = t >> 6;
    float acc[UQ];
    #pragma unroll
    for (int j = 0; j < UQ; ++j) acc[j] = 0.f;
    for (int kb = g * 4; kb < L; kb += 16) {
        size_t vb = ((size_t)(b * L + kb) * H + h) * D + d;
        float v0 = V[vb];
        float v1 = V[vb + (size_t)H * D];
        float v2 = V[vb + (size_t)2 * H * D];
        float v3 = V[vb + (size_t)3 * H * D];
        #pragma unroll
        for (int j = 0; j < UQ; ++j) {
            float4 pv = *(const float4*)(p + j * PL + kb);   // warp-uniform broadcast
            acc[j] += pv.x * v0 + pv.y * v1 + pv.z * v2 + pv.w * v3;
        }
    }
    #pragma unroll
    for (int j = 0; j < UQ; ++j) red[(g * UQ + j) * D + d] = acc[j];
    __syncthreads();

    for (int i = t; i < nq * D; i += 256) {
        int j = i >> 6, dd = i & 63;
        float s = red[(0 * UQ + j) * D + dd] + red[(1 * UQ + j) * D + dd]
                + red[(2 * UQ + j) * D + dd] + red[(3 * UQ + j) * D + dd];
        out[((size_t)(b * L + qidx[j]) * H + h) * D + dd] = s / sden[j];
    }
}

// ---------------------------------------------------------------------------
extern "C" void kernel_launch(void* const* d_in, const int* in_sizes, int n_in,
                              void* d_out, int out_size)
{
    const float* Q   = (const float*)d_in[0];
    const float* K   = (const float*)d_in[1];
    const float* V   = (const float*)d_in[2];
    const int*   idx = (const int*)d_in[3];
    float* out = (float*)d_out;

    int SK = in_sizes[3] / L;     // sample_k (= 40)
    int U  = SK;
    if (U > 64) U = 64;
    int UT = (U + UQ - 1) / UQ;

    // A: M scores (octet-parallel gathered QK over samples)
    kA_mscore<<<(BH * L) / 8, 256>>>(Q, K, idx, SK);
    // C: V mean per (b,h,d)
    kC_vmean<<<BH, 256>>>(V);
    // B: top-U query selection per (b,h)
    kB_topk<<<BH, 256>>>(U);
    // D: broadcast-fill output with Vmean
    kD_fill<<<(B * L * 128) / 256, 256>>>((float4*)out);
    // E: full attention for selected queries, overwrite their rows
    cudaFuncSetAttribute(kE_attn, cudaFuncAttributeMaxDynamicSharedMemorySize, SMEM_E);
    kE_attn<<<BH * UT, 256, SMEM_E>>>(Q, K, V, out, U, UT);
}

// round 15
// speedup vs baseline: 1.2733x; 1.2189x over previous
#include <cuda_runtime.h>
#include <cstdint>

// Problem constants (fixed by setup_inputs)
#define B 8
#define L 2048
#define H 8
#define D 64
#define BH (B*H)

// Scratch (device globals — no allocation allowed)
__device__ float g_M[BH * L];        // sparsity measure per (b,h,q)
__device__ int   g_top[BH * 64];     // top-u query indices per (b,h)  (u <= 64)
__device__ float g_vmean[BH * D];    // mean of V over L per (b,h,d)

// ---------------------------------------------------------------------------
// Kernel A v3: M[b,h,q] = max_s(QK_s) - mean_s(QK_s) over sampled keys.
// One warp per (b,h,q); each OCTET (8 lanes) handles one sample -> 4 samples
// in flight per warp. Lane ld holds float4 slices ld and ld+8 of the row
// (full 256B row per octet, coalesced LDG.128 across the warp).
// ---------------------------------------------------------------------------
__global__ void __launch_bounds__(256) kA_mscore(
    const float* __restrict__ Q, const float* __restrict__ K,
    const int* __restrict__ idx, int SK)
{
    const unsigned F = 0xffffffffu;
    int gw   = (blockIdx.x * blockDim.x + threadIdx.x) >> 5;  // [0, BH*L)
    int lane = threadIdx.x & 31;
    int oct  = lane >> 3;          // octet id: which sample of the group of 4
    int ld   = lane & 7;           // lane-in-octet: d-slice owner
    int q  = gw & (L - 1);
    int bh = gw >> 11;             // L = 2^11
    int b  = bh >> 3, h = bh & 7;

    const float4* qp = (const float4*)(Q + ((size_t)(b * L + q) * H + h) * D);
    float4 qa = qp[ld], qb = qp[ld + 8];

    const int* ip = idx + (size_t)q * SK;
    int kq0 = (lane      < SK) ? ip[lane]      : 0;
    int kq1 = (lane + 32 < SK) ? ip[lane + 32] : 0;

    float mx = -3.402823466e38f, sm = 0.f;
    int iters = (SK + 3) >> 2;

    #pragma unroll 5
    for (int it = 0; it < iters; ++it) {
        int s  = it * 4 + oct;
        int i0 = __shfl_sync(F, kq0, s & 31);
        int i1 = __shfl_sync(F, kq1, s & 31);
        int kr = (s < 32) ? i0 : i1;
        bool valid = (s < SK);
        if (!valid) kr = 0;

        const float4* kp = (const float4*)(K + ((size_t)(b * L + kr) * H + h) * D);
        float4 ka = kp[ld], kb = kp[ld + 8];
        float x = qa.x*ka.x + qa.y*ka.y + qa.z*ka.z + qa.w*ka.w
                + qb.x*kb.x + qb.y*kb.y + qb.z*kb.z + qb.w*kb.w;
        // reduce across the 8 lanes of this octet
        x += __shfl_xor_sync(F, x, 4);
        x += __shfl_xor_sync(F, x, 2);
        x += __shfl_xor_sync(F, x, 1);
        if (valid) { mx = fmaxf(mx, x); sm += x; }
    }

    // combine the 4 octet accumulators (each octet's 8 lanes are identical)
    mx = fmaxf(mx, __shfl_xor_sync(F, mx, 8));
    mx = fmaxf(mx, __shfl_xor_sync(F, mx, 16));
    sm += __shfl_xor_sync(F, sm, 8);
    sm += __shfl_xor_sync(F, sm, 16);

    if (lane == 0)
        g_M[gw] = mx - sm / (float)SK;
}

// ---------------------------------------------------------------------------
// Kernel B: top-U per (b,h), register-resident 64-bit sortable keys.
// key = (ordered(value) << 32) | ~index  -> max picks higher value, lower idx.
// ---------------------------------------------------------------------------
__global__ void __launch_bounds__(256) kB_topk(int U)
{
    __shared__ unsigned long long warpbest[8];
    __shared__ unsigned long long sbest;
    int bh = blockIdx.x, t = threadIdx.x, lane = t & 31, w = t >> 5;

    unsigned long long key[8];
    #pragma unroll
    for (int i = 0; i < 8; ++i) {
        int q = t + i * 256;
        unsigned u = __float_as_uint(g_M[(size_t)bh * L + q]);
        u ^= (u >> 31) ? 0xffffffffu : 0x80000000u;
        key[i] = ((unsigned long long)u << 32) | (unsigned)(~q);
    }

    for (int it = 0; it < U; ++it) {
        unsigned long long best = 0;
        #pragma unroll
        for (int i = 0; i < 8; ++i) best = (key[i] > best) ? key[i] : best;
        #pragma unroll
        for (int o = 16; o; o >>= 1) {
            unsigned long long oth = __shfl_xor_sync(0xffffffffu, best, o);
            best = (oth > best) ? oth : best;
        }
        if (lane == 0) warpbest[w] = best;
        __syncthreads();
        if (t < 32) {
            unsigned long long bb = (t < 8) ? warpbest[t] : 0ull;
            #pragma unroll
            for (int o = 4; o; o >>= 1) {
                unsigned long long oth = __shfl_xor_sync(0xffffffffu, bb, o);
                bb = (oth > bb) ? oth : bb;
            }
            if (t == 0) {
                sbest = bb;
                g_top[bh * 64 + it] = (int)(~(unsigned)(bb & 0xffffffffu));
            }
        }
        __syncthreads();
        unsigned long long win = sbest;
        #pragma unroll
        for (int i = 0; i < 8; ++i) if (key[i] == win) key[i] = 0ull;
    }
}

// ---------------------------------------------------------------------------
// Kernel C: Vmean[b,h,d] = mean over l of V[b,l,h,d]. One block per (b,h).
// ---------------------------------------------------------------------------
__global__ void __launch_bounds__(256) kC_vmean(const float* __restrict__ V)
{
    __shared__ float part[4][D];
    int bh = blockIdx.x, b = bh >> 3, h = bh & 7;
    int d = threadIdx.x & 63, g = threadIdx.x >> 6;
    float s = 0.f;
    for (int l = g; l < L; l += 4)
        s += V[((size_t)(b * L + l) * H + h) * D + d];
    part[g][d] = s;
    __syncthreads();
    if (threadIdx.x < D) {
        float tot = part[0][d] + part[1][d] + part[2][d] + part[3][d];
        g_vmean[bh * D + d] = tot * (1.0f / (float)L);
    }
}

// ---------------------------------------------------------------------------
// Kernel D: fill output with broadcast Vmean (1 float4 per thread — the
// measured-fastest variant).
// ---------------------------------------------------------------------------
__global__ void __launch_bounds__(256) kD_fill(float4* __restrict__ out4)
{
    int i = blockIdx.x * blockDim.x + threadIdx.x;     // [0, B*L*128)
    int j   = i & 127;          // 128 float4 per (b,l) row
    int row = i >> 7;
    int b = row >> 11;
    int h = j >> 4, d4 = j & 15;
    const float4* vm4 = (const float4*)g_vmean;
    out4[i] = vm4[(b * H + h) * 16 + d4];
}

// ---------------------------------------------------------------------------
// Kernel E: full attention for 8 selected queries per block.
// ---------------------------------------------------------------------------
#define UQ 8
#define SMEM_E ((UQ*L + UQ*D + 4*UQ*D + UQ) * 4)

__global__ void __launch_bounds__(256) kE_attn(
    const float* __restrict__ Q, const float* __restrict__ K,
    const float* __restrict__ V, float* __restrict__ out, int U, int UT)
{
    extern __shared__ float sh[];
    float* p    = sh;                    // [UQ][L] unnormalized probs
    float* Qs   = p + UQ * L;            // [UQ][D]
    float* red  = Qs + UQ * D;           // [4][UQ][D]
    float* sden = red + 4 * UQ * D;      // [UQ]
    __shared__ int qidx[UQ];

    int bh = blockIdx.x / UT, ut = blockIdx.x % UT;
    int b = bh >> 3, h = bh & 7;
    int t = threadIdx.x;
    int u0 = ut * UQ;
    int nq = U - u0; if (nq > UQ) nq = UQ;

    if (t < UQ) qidx[t] = (t < nq) ? g_top[bh * 64 + u0 + t] : 0;
    __syncthreads();

    for (int i = t; i < UQ * D; i += 256) {
        int j = i >> 6;
        Qs[i] = (j < nq) ? Q[((size_t)(b * L + qidx[j]) * H + h) * D + (i & 63)] : 0.f;
    }
    __syncthreads();

    const float scale = 0.125f;  // 1/sqrt(64)
    for (int k = t; k < L; k += 256) {
        const float4* kp = (const float4*)(K + ((size_t)(b * L + k) * H + h) * D);
        float accj[UQ];
        #pragma unroll
        for (int j = 0; j < UQ; ++j) accj[j] = 0.f;
        #pragma unroll
        for (int c = 0; c < 4; ++c) {
            float4 k0 = kp[c*4+0], k1 = kp[c*4+1], k2 = kp[c*4+2], k3 = kp[c*4+3];
            #pragma unroll
            for (int j = 0; j < UQ; ++j) {
                const float4* qf = (const float4*)(Qs + j * D) + c * 4;
                float4 q0 = qf[0], q1 = qf[1], q2 = qf[2], q3 = qf[3];
                accj[j] += q0.x*k0.x + q0.y*k0.y + q0.z*k0.z + q0.w*k0.w
                         + q1.x*k1.x + q1.y*k1.y + q1.z*k1.z + q1.w*k1.w
                         + q2.x*k2.x + q2.y*k2.y + q2.z*k2.z + q2.w*k2.w
                         + q3.x*k3.x + q3.y*k3.y + q3.z*k3.z + q3.w*k3.w;
            }
        }
        #pragma unroll
        for (int j = 0; j < UQ; ++j) p[j * L + k] = accj[j] * scale;
    }
    __syncthreads();

    int w = t >> 5, lane = t & 31;
    if (w < nq) {
        float* pr = p + w * L;
        float m = -3.402823466e38f;
        for (int k = lane; k < L; k += 32) m = fmaxf(m, pr[k]);
        #pragma unroll
        for (int o = 16; o; o >>= 1) m = fmaxf(m, __shfl_xor_sync(0xffffffffu, m, o));
        float s = 0.f;
        for (int k = lane; k < L; k += 32) {
            float e = __expf(pr[k] - m);
            pr[k] = e;
            s += e;
        }
        #pragma unroll
        for (int o = 16; o; o >>= 1) s += __shfl_xor_sync(0xffffffffu, s, o);
        if (lane == 0) sden[w] = s;
    }
    __syncthreads();

    int d = t & 63, g = t >> 6;
    float acc[UQ];
    #pragma unroll
    for (int j = 0; j < UQ; ++j) acc[j] = 0.f;
    for (int kb = g * 4; kb < L; kb += 16) {
        size_t vb = ((size_t)(b * L + kb) * H + h) * D + d;
        float v0 = V[vb];
        float v1 = V[vb + (size_t)H * D];
        float v2 = V[vb + (size_t)2 * H * D];
        float v3 = V[vb + (size_t)3 * H * D];
        #pragma unroll
        for (int j = 0; j < UQ; ++j) {
            float4 pv = *(const float4*)(p + j * L + kb);   // warp-uniform -> broadcast
            acc[j] += pv.x * v0 + pv.y * v1 + pv.z * v2 + pv.w * v3;
        }
    }
    #pragma unroll
    for (int j = 0; j < UQ; ++j) red[(g * UQ + j) * D + d] = acc[j];
    __syncthreads();

    for (int i = t; i < nq * D; i += 256) {
        int j = i >> 6, dd = i & 63;
        float s = red[(0 * UQ + j) * D + dd] + red[(1 * UQ + j) * D + dd]
                + red[(2 * UQ + j) * D + dd] + red[(3 * UQ + j) * D + dd];
        out[((size_t)(b * L + qidx[j]) * H + h) * D + dd] = s / sden[j];
    }
}

// ---------------------------------------------------------------------------
extern "C" void kernel_launch(void* const* d_in, const int* in_sizes, int n_in,
                              void* d_out, int out_size)
{
    const float* Q   = (const float*)d_in[0];
    const float* K   = (const float*)d_in[1];
    const float* V   = (const float*)d_in[2];
    const int*   idx = (const int*)d_in[3];
    float* out = (float*)d_out;

    int SK = in_sizes[3] / L;     // sample_k (= 40)
    int U  = SK;                  // u has the same formula (L_Q == L_K)
    if (U > 64) U = 64;
    int UT = (U + UQ - 1) / UQ;   // u-tiles per (b,h)

    // A: M scores (octet-parallel gathered QK over samples)
    kA_mscore<<<(BH * L) / 8, 256>>>(Q, K, idx, SK);
    // C: V mean per (b,h,d)
    kC_vmean<<<BH, 256>>>(V);
    // B: top-U query selection per (b,h)
    kB_topk<<<BH, 256>>>(U);
    // D: broadcast-fill output with Vmean
    kD_fill<<<(B * L * 128) / 256, 256>>>((float4*)out);
    // E: full attention for selected queries, overwrite their rows
    cudaFuncSetAttribute(kE_attn, cudaFuncAttributeMaxDynamicSharedMemorySize, SMEM_E);
    kE_attn<<<BH * UT, 256, SMEM_E>>>(Q, K, V, out, U, UT);
}